// round 3
// baseline (speedup 1.0000x reference)
#include <cuda_runtime.h>
#include <cuda_bf16.h>

// ---------------------------------------------------------------------------
// MultiStageDiscriminator — fp32 direct implementation, selected-stage only.
// B=16, S=4, img 1x128x128.
// Pipeline per sample b (s = stage_idx[b]):
//   x0 = leaky(conv0(img))            (64,64,64)
//   x1 = leaky(inorm(conv1(x0)))      (128,32,32)
//   q,k = 1x1 conv (16 ch), v = 1x1 conv (128 ch) on x1 (N=1024)
//   attn[n,m] = softmax_m( sum_i q[i,n]k[i,m] )
//   xa = gamma * (V @ attn^T) + x1    (128,1024)
//   x2 = leaky(inorm(conv2(xa)))      (256,16,16)
//   out = head_conv(x2)               (1,15,15)
// ---------------------------------------------------------------------------

#define B_ 16
#define SLOPE 0.2f

// ---- static scratch (no allocations allowed) ----
__device__ float g_x0[B_ * 64 * 64 * 64];      // 16 MB
__device__ float g_t1[B_ * 128 * 32 * 32];     // conv1 raw
__device__ float g_x1[B_ * 128 * 32 * 32];     // post inorm+leaky
__device__ float g_q [B_ * 16 * 1024];
__device__ float g_k [B_ * 16 * 1024];
__device__ float g_v [B_ * 128 * 1024];
__device__ float g_attn[B_ * 1024 * 1024];     // 64 MB
__device__ float g_xa[B_ * 128 * 1024];
__device__ float g_t2[B_ * 256 * 16 * 16];
__device__ float g_x2[B_ * 256 * 16 * 16];

__device__ __forceinline__ float lrelu(float v) { return v > 0.f ? v : SLOPE * v; }

// ---------------------------------------------------------------------------
// K1: conv0 (1->64, k4 s2 p1, 128->64) + leaky.  grid = B*64, block = 256
// ---------------------------------------------------------------------------
__global__ void k_conv0(const float* __restrict__ img, const int* __restrict__ sidx,
                        const float* __restrict__ w0, const float* __restrict__ b0) {
    int b  = blockIdx.x >> 6;
    int oc = blockIdx.x & 63;
    int s  = sidx[b];
    __shared__ float ws[16];
    __shared__ float bias;
    if (threadIdx.x < 16) ws[threadIdx.x] = w0[(s * 64 + oc) * 16 + threadIdx.x];
    if (threadIdx.x == 0) bias = b0[s * 64 + oc];
    __syncthreads();
    const float* im  = img + b * 128 * 128;
    float*       out = g_x0 + (b * 64 + oc) * 4096;
    for (int p = threadIdx.x; p < 4096; p += blockDim.x) {
        int oy = p >> 6, ox = p & 63;
        float acc = bias;
        #pragma unroll
        for (int ky = 0; ky < 4; ky++) {
            int iy = 2 * oy - 1 + ky;
            if ((unsigned)iy < 128u) {
                #pragma unroll
                for (int kx = 0; kx < 4; kx++) {
                    int ix = 2 * ox - 1 + kx;
                    if ((unsigned)ix < 128u)
                        acc += im[iy * 128 + ix] * ws[ky * 4 + kx];
                }
            }
        }
        out[p] = lrelu(acc);
    }
}

// ---------------------------------------------------------------------------
// K2a: conv1 (64->128, k4 s2 p1, 64->32). block handles (b, group of 8 oc),
// one thread per output spatial position. grid = B*16, block = 1024.
// ---------------------------------------------------------------------------
__global__ void k_conv1(const int* __restrict__ sidx,
                        const float* __restrict__ w1, const float* __restrict__ b1) {
    int b = blockIdx.x >> 4;
    int g = blockIdx.x & 15;
    int s = sidx[b];
    __shared__ __align__(16) float ws[64 * 16 * 8];   // [ic*16+k][8 oc] 32KB
    __shared__ float bs[8];
    for (int i = threadIdx.x; i < 64 * 16 * 8; i += blockDim.x) {
        int j = i & 7;       // oc within group
        int ick = i >> 3;    // ic*16 + k
        ws[i] = w1[(s * 128 + g * 8 + j) * 1024 + ick];
    }
    if (threadIdx.x < 8) bs[threadIdx.x] = b1[s * 128 + g * 8 + threadIdx.x];
    __syncthreads();

    int p  = threadIdx.x;          // 0..1023
    int oy = p >> 5, ox = p & 31;
    float acc[8];
    #pragma unroll
    for (int j = 0; j < 8; j++) acc[j] = bs[j];

    const float* xin = g_x0 + b * 64 * 4096;
    for (int ic = 0; ic < 64; ic++) {
        const float* xc   = xin + ic * 4096;
        const float* wrow = ws + ic * 128;
        #pragma unroll
        for (int ky = 0; ky < 4; ky++) {
            int iy = 2 * oy - 1 + ky;
            if ((unsigned)iy < 64u) {
                #pragma unroll
                for (int kx = 0; kx < 4; kx++) {
                    int ix = 2 * ox - 1 + kx;
                    if ((unsigned)ix < 64u) {
                        float v = xc[iy * 64 + ix];
                        const float* wv = wrow + (ky * 4 + kx) * 8;
                        float4 wa = *(const float4*)(wv);
                        float4 wb = *(const float4*)(wv + 4);
                        acc[0] += v * wa.x; acc[1] += v * wa.y;
                        acc[2] += v * wa.z; acc[3] += v * wa.w;
                        acc[4] += v * wb.x; acc[5] += v * wb.y;
                        acc[6] += v * wb.z; acc[7] += v * wb.w;
                    }
                }
            }
        }
    }
    float* out = g_t1 + (b * 128 + g * 8) * 1024;
    #pragma unroll
    for (int j = 0; j < 8; j++) out[j * 1024 + p] = acc[j];
}

// ---------------------------------------------------------------------------
// Instance norm + leaky. One block per (b,c), N spatial elems.
// ---------------------------------------------------------------------------
__device__ __forceinline__ void inorm_block(const float* x, float* y, int N) {
    float s = 0.f, s2 = 0.f;
    for (int i = threadIdx.x; i < N; i += blockDim.x) {
        float v = x[i]; s += v; s2 += v * v;
    }
    __shared__ float rs[8], rs2[8];
    #pragma unroll
    for (int o = 16; o; o >>= 1) {
        s  += __shfl_down_sync(~0u, s, o);
        s2 += __shfl_down_sync(~0u, s2, o);
    }
    int w = threadIdx.x >> 5, l = threadIdx.x & 31;
    if (l == 0) { rs[w] = s; rs2[w] = s2; }
    __syncthreads();
    if (w == 0) {
        s  = (l < (int)(blockDim.x >> 5)) ? rs[l]  : 0.f;
        s2 = (l < (int)(blockDim.x >> 5)) ? rs2[l] : 0.f;
        #pragma unroll
        for (int o = 4; o; o >>= 1) {
            s  += __shfl_down_sync(~0u, s, o);
            s2 += __shfl_down_sync(~0u, s2, o);
        }
        if (l == 0) {
            float m   = s / (float)N;
            float var = s2 / (float)N - m * m;
            rs[0]  = m;
            rs2[0] = rsqrtf(var + 1e-5f);
        }
    }
    __syncthreads();
    float m = rs[0], inv = rs2[0];
    for (int i = threadIdx.x; i < N; i += blockDim.x)
        y[i] = lrelu((x[i] - m) * inv);
}

__global__ void k_inorm1() {   // grid = B*128, block 256, N=1024
    int bc = blockIdx.x;
    inorm_block(g_t1 + bc * 1024, g_x1 + bc * 1024, 1024);
}
__global__ void k_inorm2() {   // grid = B*256, block 256, N=256
    int bc = blockIdx.x;
    inorm_block(g_t2 + bc * 256, g_x2 + bc * 256, 256);
}

// ---------------------------------------------------------------------------
// K3: q/k/v 1x1 convs. 160 output channels per sample in groups of 16.
// grid = B*10, block = 256 (each thread iterates over n).
// ---------------------------------------------------------------------------
__global__ void k_qkv(const int* __restrict__ sidx,
                      const float* __restrict__ wq, const float* __restrict__ bq,
                      const float* __restrict__ wk, const float* __restrict__ bk,
                      const float* __restrict__ wv, const float* __restrict__ bv) {
    int b = blockIdx.x / 10;
    int g = blockIdx.x % 10;
    int s = sidx[b];
    const float *W, *Bp;
    float* out;
    if (g == 0)      { W = wq + s * 16 * 128;  Bp = bq + s * 16;  out = g_q + b * 16 * 1024; }
    else if (g == 1) { W = wk + s * 16 * 128;  Bp = bk + s * 16;  out = g_k + b * 16 * 1024; }
    else {
        int ch0 = (g - 2) * 16;
        W   = wv + (s * 128 + ch0) * 128;
        Bp  = bv + s * 128 + ch0;
        out = g_v + (b * 128 + ch0) * 1024;
    }
    __shared__ __align__(16) float ws[128 * 16];   // [c][ch]
    __shared__ float bsm[16];
    for (int i = threadIdx.x; i < 2048; i += blockDim.x) {
        int ch = i & 15, c = i >> 4;
        ws[i] = W[ch * 128 + c];
    }
    if (threadIdx.x < 16) bsm[threadIdx.x] = Bp[threadIdx.x];
    __syncthreads();

    const float* x = g_x1 + b * 128 * 1024;
    for (int n = threadIdx.x; n < 1024; n += blockDim.x) {
        float acc[16];
        #pragma unroll
        for (int j = 0; j < 16; j++) acc[j] = bsm[j];
        for (int c = 0; c < 128; c++) {
            float v = x[c * 1024 + n];
            const float* wr = ws + c * 16;
            #pragma unroll
            for (int j = 0; j < 16; j += 4) {
                float4 w4 = *(const float4*)(wr + j);
                acc[j]     += v * w4.x; acc[j + 1] += v * w4.y;
                acc[j + 2] += v * w4.z; acc[j + 3] += v * w4.w;
            }
        }
        #pragma unroll
        for (int j = 0; j < 16; j++) out[j * 1024 + n] = acc[j];
    }
}

// ---------------------------------------------------------------------------
// K4: energies + row softmax. Block handles (b, 8 rows of n). grid = B*128,
// block = 256. e[n,m] = sum_i q[i,n]k[i,m]; softmax over m; write to g_attn.
// ---------------------------------------------------------------------------
__global__ void k_attn_sm() {
    int b  = blockIdx.x >> 7;
    int n0 = (blockIdx.x & 127) * 8;
    __shared__ float qs[8 * 16];
    __shared__ float es[8 * 1024];   // 32KB
    if (threadIdx.x < 128) {
        int n = threadIdx.x >> 4, i = threadIdx.x & 15;
        qs[n * 16 + i] = g_q[(b * 16 + i) * 1024 + n0 + n];
    }
    __syncthreads();
    const float* kp = g_k + b * 16 * 1024;
    for (int m = threadIdx.x; m < 1024; m += 256) {
        float kv[16];
        #pragma unroll
        for (int i = 0; i < 16; i++) kv[i] = kp[i * 1024 + m];
        #pragma unroll
        for (int n = 0; n < 8; n++) {
            float e = 0.f;
            #pragma unroll
            for (int i = 0; i < 16; i++) e += qs[n * 16 + i] * kv[i];
            es[n * 1024 + m] = e;
        }
    }
    __syncthreads();
    int w = threadIdx.x >> 5, l = threadIdx.x & 31;   // warp w owns row w
    float mx = -1e30f;
    for (int m = l; m < 1024; m += 32) mx = fmaxf(mx, es[w * 1024 + m]);
    #pragma unroll
    for (int o = 16; o; o >>= 1) mx = fmaxf(mx, __shfl_xor_sync(~0u, mx, o));
    float sum = 0.f;
    for (int m = l; m < 1024; m += 32) {
        float p = __expf(es[w * 1024 + m] - mx);
        es[w * 1024 + m] = p;
        sum += p;
    }
    #pragma unroll
    for (int o = 16; o; o >>= 1) sum += __shfl_xor_sync(~0u, sum, o);
    float r = 1.f / sum;
    float* out = g_attn + ((size_t)b * 1024 + n0 + w) * 1024;
    for (int m = l; m < 1024; m += 32) out[m] = es[w * 1024 + m] * r;
}

// ---------------------------------------------------------------------------
// K5: xa = gamma * (V @ attn^T) + x1.  Tiled GEMM: 64c x 64n tile, k-chunk 16.
// grid = (16 n-tiles, 2 c-tiles, B), block = 256 (16x16 threads, 4x4 micro).
// ---------------------------------------------------------------------------
__global__ void k_av(const int* __restrict__ sidx, const float* __restrict__ gamma) {
    int b  = blockIdx.z;
    int c0 = blockIdx.y * 64;
    int n0 = blockIdx.x * 64;
    float gm = gamma[sidx[b]];
    const float* V = g_v + b * 128 * 1024;
    const float* P = g_attn + (size_t)b * 1024 * 1024;
    __shared__ __align__(16) float As[16][64];   // V chunk  [m][c]
    __shared__ __align__(16) float Bs[16][64];   // P chunk  [m][n]
    float acc[4][4] = {};
    int tx = threadIdx.x & 15, ty = threadIdx.x >> 4;

    for (int m0 = 0; m0 < 1024; m0 += 16) {
        #pragma unroll
        for (int r = 0; r < 4; r++) {
            int idx = threadIdx.x + r * 256;
            int mm = idx & 15, cc = idx >> 4;
            As[mm][cc] = V[(c0 + cc) * 1024 + m0 + mm];
            Bs[mm][cc] = P[(n0 + cc) * 1024 + m0 + mm];
        }
        __syncthreads();
        #pragma unroll
        for (int kk = 0; kk < 16; kk++) {
            float4 a  = *(const float4*)&As[kk][ty * 4];
            float4 bb = *(const float4*)&Bs[kk][tx * 4];
            acc[0][0] += a.x * bb.x; acc[0][1] += a.x * bb.y; acc[0][2] += a.x * bb.z; acc[0][3] += a.x * bb.w;
            acc[1][0] += a.y * bb.x; acc[1][1] += a.y * bb.y; acc[1][2] += a.y * bb.z; acc[1][3] += a.y * bb.w;
            acc[2][0] += a.z * bb.x; acc[2][1] += a.z * bb.y; acc[2][2] += a.z * bb.z; acc[2][3] += a.z * bb.w;
            acc[3][0] += a.w * bb.x; acc[3][1] += a.w * bb.y; acc[3][2] += a.w * bb.z; acc[3][3] += a.w * bb.w;
        }
        __syncthreads();
    }

    const float* X = g_x1 + b * 128 * 1024;
    float*       O = g_xa + b * 128 * 1024;
    #pragma unroll
    for (int i = 0; i < 4; i++) {
        int c = c0 + ty * 4 + i;
        #pragma unroll
        for (int j = 0; j < 4; j++) {
            int n = n0 + tx * 4 + j;
            O[c * 1024 + n] = gm * acc[i][j] + X[c * 1024 + n];
        }
    }
}

// ---------------------------------------------------------------------------
// K6a: conv2 (128->256, k4 s2 p1, 32->16). block handles (b, group of 4 oc),
// one thread per output spatial position. grid = B*64, block = 256.
// ---------------------------------------------------------------------------
__global__ void k_conv2(const int* __restrict__ sidx,
                        const float* __restrict__ w2, const float* __restrict__ b2) {
    int b = blockIdx.x >> 6;
    int g = blockIdx.x & 63;
    int s = sidx[b];
    __shared__ __align__(16) float ws[128 * 16 * 4];   // [ic*16+k][4 oc] 32KB
    __shared__ float bs[4];
    for (int i = threadIdx.x; i < 128 * 16 * 4; i += blockDim.x) {
        int j = i & 3;
        int ick = i >> 2;
        ws[i] = w2[(s * 256 + g * 4 + j) * 2048 + ick];
    }
    if (threadIdx.x < 4) bs[threadIdx.x] = b2[s * 256 + g * 4 + threadIdx.x];
    __syncthreads();

    int oy = threadIdx.x >> 4, ox = threadIdx.x & 15;
    float acc[4] = { bs[0], bs[1], bs[2], bs[3] };
    const float* xin = g_xa + b * 128 * 1024;
    for (int ic = 0; ic < 128; ic++) {
        const float* xc = xin + ic * 1024;
        const float* wr = ws + ic * 64;
        #pragma unroll
        for (int ky = 0; ky < 4; ky++) {
            int iy = 2 * oy - 1 + ky;
            if ((unsigned)iy < 32u) {
                #pragma unroll
                for (int kx = 0; kx < 4; kx++) {
                    int ix = 2 * ox - 1 + kx;
                    if ((unsigned)ix < 32u) {
                        float v = xc[iy * 32 + ix];
                        float4 w4 = *(const float4*)(wr + (ky * 4 + kx) * 4);
                        acc[0] += v * w4.x; acc[1] += v * w4.y;
                        acc[2] += v * w4.z; acc[3] += v * w4.w;
                    }
                }
            }
        }
    }
    float* out = g_t2 + (b * 256 + g * 4) * 256;
    #pragma unroll
    for (int j = 0; j < 4; j++) out[j * 256 + threadIdx.x] = acc[j];
}

// ---------------------------------------------------------------------------
// K7: head conv (256->1, k4 s1 p1, 16->15). grid = B, block = 256 (225 used).
// ---------------------------------------------------------------------------
__global__ void k_head(const int* __restrict__ sidx,
                       const float* __restrict__ wh, const float* __restrict__ bh,
                       float* __restrict__ out) {
    int b = blockIdx.x;
    int s = sidx[b];
    __shared__ float ws[256 * 16];   // 16KB
    for (int i = threadIdx.x; i < 4096; i += blockDim.x) ws[i] = wh[s * 4096 + i];
    __shared__ float bias;
    if (threadIdx.x == 0) bias = bh[s];
    __syncthreads();
    if (threadIdx.x < 225) {
        int oy = threadIdx.x / 15, ox = threadIdx.x % 15;
        float acc = bias;
        const float* x = g_x2 + b * 256 * 256;
        for (int ic = 0; ic < 256; ic++) {
            const float* xc = x + ic * 256;
            const float* wr = ws + ic * 16;
            #pragma unroll
            for (int ky = 0; ky < 4; ky++) {
                int iy = oy - 1 + ky;
                if ((unsigned)iy < 16u) {
                    #pragma unroll
                    for (int kx = 0; kx < 4; kx++) {
                        int ix = ox - 1 + kx;
                        if ((unsigned)ix < 16u)
                            acc += xc[iy * 16 + ix] * wr[ky * 4 + kx];
                    }
                }
            }
        }
        out[b * 225 + threadIdx.x] = acc;
    }
}

// ---------------------------------------------------------------------------
extern "C" void kernel_launch(void* const* d_in, const int* in_sizes, int n_in,
                              void* d_out, int out_size) {
    const float* img  = (const float*)d_in[0];
    const int*   sidx = (const int*)  d_in[1];
    const float* w0 = (const float*)d_in[2];
    const float* b0 = (const float*)d_in[3];
    const float* w1 = (const float*)d_in[4];
    const float* b1 = (const float*)d_in[5];
    const float* w2 = (const float*)d_in[6];
    const float* b2 = (const float*)d_in[7];
    const float* wq = (const float*)d_in[8];
    const float* bq = (const float*)d_in[9];
    const float* wk = (const float*)d_in[10];
    const float* bk = (const float*)d_in[11];
    const float* wv = (const float*)d_in[12];
    const float* bv = (const float*)d_in[13];
    const float* gamma = (const float*)d_in[14];
    const float* wh = (const float*)d_in[15];
    const float* bh = (const float*)d_in[16];
    float* out = (float*)d_out;

    k_conv0   <<<B_ * 64, 256>>>(img, sidx, w0, b0);
    k_conv1   <<<B_ * 16, 1024>>>(sidx, w1, b1);
    k_inorm1  <<<B_ * 128, 256>>>();
    k_qkv     <<<B_ * 10, 256>>>(sidx, wq, bq, wk, bk, wv, bv);
    k_attn_sm <<<B_ * 128, 256>>>();
    k_av      <<<dim3(16, 2, B_), 256>>>(sidx, gamma);
    k_conv2   <<<B_ * 64, 256>>>(sidx, w2, b2);
    k_inorm2  <<<B_ * 256, 256>>>();
    k_head    <<<B_, 256>>>(sidx, wh, bh, out);
}

// round 6
// speedup vs baseline: 1.2049x; 1.2049x over previous
#include <cuda_runtime.h>
#include <cuda_bf16.h>

// ---------------------------------------------------------------------------
// MultiStageDiscriminator — fp32, selected-stage only, fused norms, padded acts.
// ---------------------------------------------------------------------------

#define B_ 16
#define SLOPE 0.2f

// ---- static scratch (zero-initialized; padded borders are never written) ----
__device__ float g_x0p[B_ * 64 * 66 * 66];     // conv0 out, padded 66x66 (~17.8MB)
__device__ float g_x1 [B_ * 128 * 1024];       // post inorm+leaky
__device__ float g_q  [B_ * 16 * 1024];
__device__ float g_k  [B_ * 16 * 1024];
__device__ float g_v  [B_ * 128 * 1024];
__device__ float g_attn[B_ * 1024 * 1024];     // 64 MB
__device__ float g_xap[B_ * 128 * 34 * 34];    // attn residual out, padded 34x34
__device__ float g_x2 [B_ * 256 * 16 * 16];

__device__ __forceinline__ float lrelu(float v) { return v > 0.f ? v : SLOPE * v; }

// ---------------------------------------------------------------------------
// K1: conv0 (1->64, k4 s2 p1, 128->64) + leaky -> padded 66x66.
// grid = B*64, block = 256
// ---------------------------------------------------------------------------
__global__ void k_conv0(const float* __restrict__ img, const int* __restrict__ sidx,
                        const float* __restrict__ w0, const float* __restrict__ b0) {
    int b  = blockIdx.x >> 6;
    int oc = blockIdx.x & 63;
    int s  = sidx[b];
    __shared__ float ws[16];
    __shared__ float bias;
    if (threadIdx.x < 16) ws[threadIdx.x] = w0[(s * 64 + oc) * 16 + threadIdx.x];
    if (threadIdx.x == 0) bias = b0[s * 64 + oc];
    __syncthreads();
    const float* im  = img + b * 128 * 128;
    float*       out = g_x0p + (b * 64 + oc) * 4356;
    for (int p = threadIdx.x; p < 4096; p += blockDim.x) {
        int oy = p >> 6, ox = p & 63;
        float acc = bias;
        #pragma unroll
        for (int ky = 0; ky < 4; ky++) {
            int iy = 2 * oy - 1 + ky;
            if ((unsigned)iy < 128u) {
                #pragma unroll
                for (int kx = 0; kx < 4; kx++) {
                    int ix = 2 * ox - 1 + kx;
                    if ((unsigned)ix < 128u)
                        acc += im[iy * 128 + ix] * ws[ky * 4 + kx];
                }
            }
        }
        out[(oy + 1) * 66 + ox + 1] = lrelu(acc);
    }
}

// ---------------------------------------------------------------------------
// K2: conv1 (64->128, k4 s2 p1, 64->32) + FUSED instance-norm + leaky.
// Block = 1024 threads (all spatial positions), 8 oc/block. grid = B*16.
// Padded input -> no boundary predicates.
// ---------------------------------------------------------------------------
__global__ void __launch_bounds__(1024, 1)
k_conv1(const int* __restrict__ sidx,
        const float* __restrict__ w1, const float* __restrict__ b1) {
    int b = blockIdx.x >> 4;
    int g = blockIdx.x & 15;
    int s = sidx[b];
    __shared__ __align__(16) float ws[64 * 16 * 8];   // [ic*16+k][8 oc] 32KB
    __shared__ float bs[8];
    for (int i = threadIdx.x; i < 64 * 16 * 8; i += blockDim.x) {
        int j = i & 7;       // oc within group
        int ick = i >> 3;    // ic*16 + k
        ws[i] = w1[(s * 128 + g * 8 + j) * 1024 + ick];
    }
    if (threadIdx.x < 8) bs[threadIdx.x] = b1[s * 128 + g * 8 + threadIdx.x];
    __syncthreads();

    int p  = threadIdx.x;          // 0..1023
    int oy = p >> 5, ox = p & 31;
    float acc[8];
    #pragma unroll
    for (int j = 0; j < 8; j++) acc[j] = bs[j];

    const float* xin = g_x0p + b * 64 * 4356 + (2 * oy) * 66 + 2 * ox;
    for (int ic = 0; ic < 64; ic++) {
        const float* xc   = xin + ic * 4356;
        const float* wrow = ws + ic * 128;
        #pragma unroll
        for (int ky = 0; ky < 4; ky++) {
            #pragma unroll
            for (int kx = 0; kx < 4; kx++) {
                float v = xc[ky * 66 + kx];
                const float* wv = wrow + (ky * 4 + kx) * 8;
                float4 wa = *(const float4*)(wv);
                float4 wb = *(const float4*)(wv + 4);
                acc[0] += v * wa.x; acc[1] += v * wa.y;
                acc[2] += v * wa.z; acc[3] += v * wa.w;
                acc[4] += v * wb.x; acc[5] += v * wb.y;
                acc[6] += v * wb.z; acc[7] += v * wb.w;
            }
        }
    }

    // fused instance norm over the 1024 positions of each of the 8 channels
    __shared__ float wsum[32][8], wsum2[32][8];
    int w = threadIdx.x >> 5, l = threadIdx.x & 31;
    #pragma unroll
    for (int j = 0; j < 8; j++) {
        float sv = acc[j], qv = acc[j] * acc[j];
        #pragma unroll
        for (int o = 16; o; o >>= 1) {
            sv += __shfl_down_sync(~0u, sv, o);
            qv += __shfl_down_sync(~0u, qv, o);
        }
        if (l == 0) { wsum[w][j] = sv; wsum2[w][j] = qv; }
    }
    __syncthreads();
    __shared__ float mean_s[8], inv_s[8];
    if (threadIdx.x < 8) {
        int j = threadIdx.x;
        float sv = 0.f, qv = 0.f;
        #pragma unroll
        for (int ww = 0; ww < 32; ww++) { sv += wsum[ww][j]; qv += wsum2[ww][j]; }
        float m = sv * (1.f / 1024.f);
        float v = qv * (1.f / 1024.f) - m * m;
        mean_s[j] = m;
        inv_s[j]  = rsqrtf(v + 1e-5f);
    }
    __syncthreads();
    float* out = g_x1 + (b * 128 + g * 8) * 1024;
    #pragma unroll
    for (int j = 0; j < 8; j++)
        out[j * 1024 + p] = lrelu((acc[j] - mean_s[j]) * inv_s[j]);
}

// ---------------------------------------------------------------------------
// K3: q/k/v 1x1 convs. grid = (4 n-tiles, 10 groups, B), block = 256.
// ---------------------------------------------------------------------------
__global__ void k_qkv(const int* __restrict__ sidx,
                      const float* __restrict__ wq, const float* __restrict__ bq,
                      const float* __restrict__ wk, const float* __restrict__ bk,
                      const float* __restrict__ wv, const float* __restrict__ bv) {
    int b = blockIdx.z;
    int g = blockIdx.y;
    int s = sidx[b];
    const float *W, *Bp;
    float* out;
    if (g == 0)      { W = wq + s * 16 * 128;  Bp = bq + s * 16;  out = g_q + b * 16 * 1024; }
    else if (g == 1) { W = wk + s * 16 * 128;  Bp = bk + s * 16;  out = g_k + b * 16 * 1024; }
    else {
        int ch0 = (g - 2) * 16;
        W   = wv + (s * 128 + ch0) * 128;
        Bp  = bv + s * 128 + ch0;
        out = g_v + (b * 128 + ch0) * 1024;
    }
    __shared__ __align__(16) float ws[128 * 16];   // [c][ch]
    __shared__ float bsm[16];
    for (int i = threadIdx.x; i < 2048; i += blockDim.x) {
        int ch = i & 15, c = i >> 4;
        ws[i] = W[ch * 128 + c];
    }
    if (threadIdx.x < 16) bsm[threadIdx.x] = Bp[threadIdx.x];
    __syncthreads();

    const float* x = g_x1 + b * 128 * 1024;
    int n = blockIdx.x * 256 + threadIdx.x;
    float acc[16];
    #pragma unroll
    for (int j = 0; j < 16; j++) acc[j] = bsm[j];
    for (int c = 0; c < 128; c++) {
        float v = x[c * 1024 + n];
        const float* wr = ws + c * 16;
        #pragma unroll
        for (int j = 0; j < 16; j += 4) {
            float4 w4 = *(const float4*)(wr + j);
            acc[j]     += v * w4.x; acc[j + 1] += v * w4.y;
            acc[j + 2] += v * w4.z; acc[j + 3] += v * w4.w;
        }
    }
    #pragma unroll
    for (int j = 0; j < 16; j++) out[j * 1024 + n] = acc[j];
}

// ---------------------------------------------------------------------------
// K4: energies + row softmax. Block handles (b, 8 rows of n). grid = B*128,
// block = 256.
// ---------------------------------------------------------------------------
__global__ void k_attn_sm() {
    int b  = blockIdx.x >> 7;
    int n0 = (blockIdx.x & 127) * 8;
    __shared__ float qs[8 * 16];
    __shared__ float es[8 * 1024];   // 32KB
    if (threadIdx.x < 128) {
        int n = threadIdx.x >> 4, i = threadIdx.x & 15;
        qs[n * 16 + i] = g_q[(b * 16 + i) * 1024 + n0 + n];
    }
    __syncthreads();
    const float* kp = g_k + b * 16 * 1024;
    for (int m = threadIdx.x; m < 1024; m += 256) {
        float kv[16];
        #pragma unroll
        for (int i = 0; i < 16; i++) kv[i] = kp[i * 1024 + m];
        #pragma unroll
        for (int n = 0; n < 8; n++) {
            float e = 0.f;
            #pragma unroll
            for (int i = 0; i < 16; i++) e += qs[n * 16 + i] * kv[i];
            es[n * 1024 + m] = e;
        }
    }
    __syncthreads();
    int w = threadIdx.x >> 5, l = threadIdx.x & 31;   // warp w owns row w
    float mx = -1e30f;
    for (int m = l; m < 1024; m += 32) mx = fmaxf(mx, es[w * 1024 + m]);
    #pragma unroll
    for (int o = 16; o; o >>= 1) mx = fmaxf(mx, __shfl_xor_sync(~0u, mx, o));
    float sum = 0.f;
    for (int m = l; m < 1024; m += 32) {
        float p = __expf(es[w * 1024 + m] - mx);
        es[w * 1024 + m] = p;
        sum += p;
    }
    #pragma unroll
    for (int o = 16; o; o >>= 1) sum += __shfl_xor_sync(~0u, sum, o);
    float r = 1.f / sum;
    float* out = g_attn + ((size_t)b * 1024 + n0 + w) * 1024;
    for (int m = l; m < 1024; m += 32) out[m] = es[w * 1024 + m] * r;
}

// ---------------------------------------------------------------------------
// K5: xa = gamma * (V @ attn^T) + x1, written to PADDED 34x34 layout.
// Tile: 128c x 64n, k-chunk 16, 8x4 micro. grid = (16, 1, B), block = 256.
// ---------------------------------------------------------------------------
__global__ void k_av(const int* __restrict__ sidx, const float* __restrict__ gamma) {
    int b  = blockIdx.z;
    int n0 = blockIdx.x * 64;
    float gm = gamma[sidx[b]];
    const float* V = g_v + b * 128 * 1024;
    const float* P = g_attn + (size_t)b * 1024 * 1024;
    __shared__ __align__(16) float As[16][132];   // V chunk  [m][c]
    __shared__ __align__(16) float Bs[16][68];    // P chunk  [m][n]
    float acc[8][4] = {};
    int tx = threadIdx.x & 15;   // n micro
    int ty = threadIdx.x >> 4;   // c micro
    int mm = threadIdx.x & 15;
    int c0 = threadIdx.x >> 4;   // 0..15

    for (int m0 = 0; m0 < 1024; m0 += 16) {
        #pragma unroll
        for (int r = 0; r < 8; r++) {
            int cc = c0 + r * 16;
            As[mm][cc] = V[cc * 1024 + m0 + mm];
        }
        #pragma unroll
        for (int r = 0; r < 4; r++) {
            int nn = c0 + r * 16;
            Bs[mm][nn] = P[(size_t)(n0 + nn) * 1024 + m0 + mm];
        }
        __syncthreads();
        #pragma unroll
        for (int kk = 0; kk < 16; kk++) {
            float4 a0 = *(const float4*)&As[kk][ty * 8];
            float4 a1 = *(const float4*)&As[kk][ty * 8 + 4];
            float4 bb = *(const float4*)&Bs[kk][tx * 4];
            float av[8] = {a0.x, a0.y, a0.z, a0.w, a1.x, a1.y, a1.z, a1.w};
            float bv[4] = {bb.x, bb.y, bb.z, bb.w};
            #pragma unroll
            for (int i = 0; i < 8; i++)
                #pragma unroll
                for (int j = 0; j < 4; j++)
                    acc[i][j] += av[i] * bv[j];
        }
        __syncthreads();
    }

    const float* X = g_x1 + b * 128 * 1024;
    float*       O = g_xap + b * 128 * 1156;
    #pragma unroll
    for (int i = 0; i < 8; i++) {
        int c = ty * 8 + i;
        #pragma unroll
        for (int j = 0; j < 4; j++) {
            int n = n0 + tx * 4 + j;
            int y = n >> 5, x = n & 31;
            O[c * 1156 + (y + 1) * 34 + x + 1] = gm * acc[i][j] + X[c * 1024 + n];
        }
    }
}

// ---------------------------------------------------------------------------
// K6: conv2 (128->256, k4 s2 p1, 32->16) + FUSED instance-norm + leaky.
// Block = 256 threads (all positions), 4 oc/block. grid = B*64.
// ---------------------------------------------------------------------------
__global__ void k_conv2(const int* __restrict__ sidx,
                        const float* __restrict__ w2, const float* __restrict__ b2) {
    int b = blockIdx.x >> 6;
    int g = blockIdx.x & 63;
    int s = sidx[b];
    __shared__ __align__(16) float ws[128 * 16 * 4];   // [ic*16+k][4 oc] 32KB
    __shared__ float bs[4];
    for (int i = threadIdx.x; i < 128 * 16 * 4; i += blockDim.x) {
        int j = i & 3;
        int ick = i >> 2;
        ws[i] = w2[(s * 256 + g * 4 + j) * 2048 + ick];
    }
    if (threadIdx.x < 4) bs[threadIdx.x] = b2[s * 256 + g * 4 + threadIdx.x];
    __syncthreads();

    int oy = threadIdx.x >> 4, ox = threadIdx.x & 15;
    float acc[4] = { bs[0], bs[1], bs[2], bs[3] };
    const float* xin = g_xap + b * 128 * 1156 + (2 * oy) * 34 + 2 * ox;
    for (int ic = 0; ic < 128; ic++) {
        const float* xc = xin + ic * 1156;
        const float* wr = ws + ic * 64;
        #pragma unroll
        for (int ky = 0; ky < 4; ky++) {
            #pragma unroll
            for (int kx = 0; kx < 4; kx++) {
                float v = xc[ky * 34 + kx];
                float4 w4 = *(const float4*)(wr + (ky * 4 + kx) * 4);
                acc[0] += v * w4.x; acc[1] += v * w4.y;
                acc[2] += v * w4.z; acc[3] += v * w4.w;
            }
        }
    }

    // fused instance norm over the 256 positions of each of the 4 channels
    __shared__ float wsum[8][4], wsum2[8][4];
    int w = threadIdx.x >> 5, l = threadIdx.x & 31;
    #pragma unroll
    for (int j = 0; j < 4; j++) {
        float sv = acc[j], qv = acc[j] * acc[j];
        #pragma unroll
        for (int o = 16; o; o >>= 1) {
            sv += __shfl_down_sync(~0u, sv, o);
            qv += __shfl_down_sync(~0u, qv, o);
        }
        if (l == 0) { wsum[w][j] = sv; wsum2[w][j] = qv; }
    }
    __syncthreads();
    __shared__ float mean_s[4], inv_s[4];
    if (threadIdx.x < 4) {
        int j = threadIdx.x;
        float sv = 0.f, qv = 0.f;
        #pragma unroll
        for (int ww = 0; ww < 8; ww++) { sv += wsum[ww][j]; qv += wsum2[ww][j]; }
        float m = sv * (1.f / 256.f);
        float v = qv * (1.f / 256.f) - m * m;
        mean_s[j] = m;
        inv_s[j]  = rsqrtf(v + 1e-5f);
    }
    __syncthreads();
    float* out = g_x2 + (b * 256 + g * 4) * 256;
    #pragma unroll
    for (int j = 0; j < 4; j++)
        out[j * 256 + threadIdx.x] = lrelu((acc[j] - mean_s[j]) * inv_s[j]);
}

// ---------------------------------------------------------------------------
// K7: head conv (256->1, k4 s1 p1, 16->15). grid = B, block = 256 (225 used).
// ---------------------------------------------------------------------------
__global__ void k_head(const int* __restrict__ sidx,
                       const float* __restrict__ wh, const float* __restrict__ bh,
                       float* __restrict__ out) {
    int b = blockIdx.x;
    int s = sidx[b];
    __shared__ float ws[256 * 16];   // 16KB
    for (int i = threadIdx.x; i < 4096; i += blockDim.x) ws[i] = wh[s * 4096 + i];
    __shared__ float bias;
    if (threadIdx.x == 0) bias = bh[s];
    __syncthreads();
    if (threadIdx.x < 225) {
        int oy = threadIdx.x / 15, ox = threadIdx.x % 15;
        float acc = bias;
        const float* x = g_x2 + b * 256 * 256;
        for (int ic = 0; ic < 256; ic++) {
            const float* xc = x + ic * 256;
            const float* wr = ws + ic * 16;
            #pragma unroll
            for (int ky = 0; ky < 4; ky++) {
                int iy = oy - 1 + ky;
                if ((unsigned)iy < 16u) {
                    #pragma unroll
                    for (int kx = 0; kx < 4; kx++) {
                        int ix = ox - 1 + kx;
                        if ((unsigned)ix < 16u)
                            acc += xc[iy * 16 + ix] * wr[ky * 4 + kx];
                    }
                }
            }
        }
        out[b * 225 + threadIdx.x] = acc;
    }
}

// ---------------------------------------------------------------------------
extern "C" void kernel_launch(void* const* d_in, const int* in_sizes, int n_in,
                              void* d_out, int out_size) {
    const float* img  = (const float*)d_in[0];
    const int*   sidx = (const int*)  d_in[1];
    const float* w0 = (const float*)d_in[2];
    const float* b0 = (const float*)d_in[3];
    const float* w1 = (const float*)d_in[4];
    const float* b1 = (const float*)d_in[5];
    const float* w2 = (const float*)d_in[6];
    const float* b2 = (const float*)d_in[7];
    const float* wq = (const float*)d_in[8];
    const float* bq = (const float*)d_in[9];
    const float* wk = (const float*)d_in[10];
    const float* bk = (const float*)d_in[11];
    const float* wv = (const float*)d_in[12];
    const float* bv = (const float*)d_in[13];
    const float* gamma = (const float*)d_in[14];
    const float* wh = (const float*)d_in[15];
    const float* bh = (const float*)d_in[16];
    float* out = (float*)d_out;

    k_conv0   <<<B_ * 64, 256>>>(img, sidx, w0, b0);
    k_conv1   <<<B_ * 16, 1024>>>(sidx, w1, b1);
    k_qkv     <<<dim3(4, 10, B_), 256>>>(sidx, wq, bq, wk, bk, wv, bv);
    k_attn_sm <<<B_ * 128, 256>>>();
    k_av      <<<dim3(16, 1, B_), 256>>>(sidx, gamma);
    k_conv2   <<<B_ * 64, 256>>>(sidx, w2, b2);
    k_head    <<<B_, 256>>>(sidx, wh, bh, out);
}